// round 8
// baseline (speedup 1.0000x reference)
#include <cuda_runtime.h>
#include <cuda_bf16.h>
#include <cstdint>

// HardBinaryVote: inputs [V=31, B=2,000,000] row-major {0,1} (int32 or f32 —
// vote == (bits != 0) either way); out[b] (FLOAT32) = majority = (2*ones > V).
//
// R8: single perfectly-balanced wave. grid = ceil(n4/2/256) = 977 CTAs
// (< 1184 resident capacity at 7-8 CTAs/SM), each thread owns exactly TWO
// uint4 columns (idx and idx+half) -> no wave transition, no tail imbalance,
// 62 front-batched LDG.128/thread. Streaming .cs loads/stores.

static constexpr int THREADS = 256;

template <int V>
__global__ __launch_bounds__(THREADS, 7)
void vote_vec4_x2(const uint4* __restrict__ in4,
                  float4* __restrict__ out4,
                  int n4, int half) {
    const int idx = blockIdx.x * THREADS + threadIdx.x;
    if (idx >= half) return;

    const int i0 = idx;
    const int i1 = idx + half;
    const bool has2 = (i1 < n4);

    int a0 = 0, a1 = 0, a2 = 0, a3 = 0;   // column i0
    int b0 = 0, b1 = 0, b2 = 0, b3 = 0;   // column i1

#pragma unroll
    for (int v = 0; v < V; v++) {
        const long long roff = (long long)v * n4;
        uint4 x = __ldcs(&in4[roff + i0]);
        a0 += (x.x != 0u); a1 += (x.y != 0u);
        a2 += (x.z != 0u); a3 += (x.w != 0u);
        if (has2) {
            uint4 y = __ldcs(&in4[roff + i1]);
            b0 += (y.x != 0u); b1 += (y.y != 0u);
            b2 += (y.z != 0u); b3 += (y.w != 0u);
        }
    }

    float4 oa;
    oa.x = (2 * a0 > V) ? 1.0f : 0.0f;
    oa.y = (2 * a1 > V) ? 1.0f : 0.0f;
    oa.z = (2 * a2 > V) ? 1.0f : 0.0f;
    oa.w = (2 * a3 > V) ? 1.0f : 0.0f;
    __stcs(&out4[i0], oa);

    if (has2) {
        float4 ob;
        ob.x = (2 * b0 > V) ? 1.0f : 0.0f;
        ob.y = (2 * b1 > V) ? 1.0f : 0.0f;
        ob.z = (2 * b2 > V) ? 1.0f : 0.0f;
        ob.w = (2 * b3 > V) ? 1.0f : 0.0f;
        __stcs(&out4[i1], ob);
    }
}

// Runtime-V vectorized fallback (one column per thread).
__global__ __launch_bounds__(THREADS)
void vote_vec4_dyn(const uint4* __restrict__ in4,
                   float4* __restrict__ out4,
                   int n4, int V) {
    const int idx = blockIdx.x * THREADS + threadIdx.x;
    if (idx >= n4) return;
    int s0 = 0, s1 = 0, s2 = 0, s3 = 0;
#pragma unroll 8
    for (int v = 0; v < V; v++) {
        uint4 x = __ldcs(&in4[(long long)v * n4 + idx]);
        s0 += (x.x != 0u); s1 += (x.y != 0u);
        s2 += (x.z != 0u); s3 += (x.w != 0u);
    }
    float4 o;
    o.x = (2 * s0 > V) ? 1.0f : 0.0f;
    o.y = (2 * s1 > V) ? 1.0f : 0.0f;
    o.z = (2 * s2 > V) ? 1.0f : 0.0f;
    o.w = (2 * s3 > V) ? 1.0f : 0.0f;
    __stcs(&out4[idx], o);
}

// Scalar fallback for B % 4 != 0.
__global__ __launch_bounds__(THREADS)
void vote_scalar(const unsigned int* __restrict__ in,
                 float* __restrict__ out,
                 int B, int V) {
    int b = blockIdx.x * THREADS + threadIdx.x;
    const int stride = gridDim.x * THREADS;
    for (; b < B; b += stride) {
        int s = 0;
        for (int v = 0; v < V; v++) s += (in[(long long)v * B + b] != 0u);
        out[b] = (2 * s > V) ? 1.0f : 0.0f;
    }
}

extern "C" void kernel_launch(void* const* d_in, const int* in_sizes, int n_in,
                              void* d_out, int out_size) {
    const unsigned int* in = (const unsigned int*)d_in[0];
    float* out = (float*)d_out;

    const long long Sin = in_sizes[0];
    long long B = out_size;
    if (B <= 0) return;
    long long V = (Sin % B == 0) ? (Sin / B) : 31;
    if (V <= 0) V = 1;

    if (B % 4 == 0) {
        const int n4 = (int)(B / 4);
        if (V == 31) {
            const int half = (n4 + 1) / 2;
            const int blocks = (half + THREADS - 1) / THREADS;
            vote_vec4_x2<31><<<blocks, THREADS>>>(
                (const uint4*)in, (float4*)out, n4, half);
        } else {
            const int blocks = (n4 + THREADS - 1) / THREADS;
            vote_vec4_dyn<<<blocks, THREADS>>>(
                (const uint4*)in, (float4*)out, n4, (int)V);
        }
    } else {
        int blocks = (int)((B + THREADS - 1) / THREADS);
        if (blocks > 148 * 32) blocks = 148 * 32;
        vote_scalar<<<blocks, THREADS>>>(in, out, (int)B, (int)V);
    }
}

// round 9
// speedup vs baseline: 1.1049x; 1.1049x over previous
#include <cuda_runtime.h>
#include <cuda_bf16.h>
#include <cstdint>

// HardBinaryVote: inputs [V=31, B=2,000,000] row-major {0,1} (int32 or f32 —
// vote == (bits != 0) either way); out[b] (FLOAT32) = majority = (2*ones > V).
//
// R9: R7 structure (1 uint4 column/thread, one-shot partition, .cs streaming,
// regs<=32, V fully unrolled) with 128-thread CTAs: same 64 resident warps/SM,
// but 2x finer CTA granularity so the final-wave drain rebalances better.

static constexpr int THREADS = 128;

template <int V>
__global__ __launch_bounds__(THREADS, 16)
void vote_vec4_oneshot(const uint4* __restrict__ in4,
                       float4* __restrict__ out4,
                       int n4) {
    const int idx = blockIdx.x * THREADS + threadIdx.x;
    if (idx >= n4) return;

    // Two independent accumulation chains per component.
    int a0 = 0, a1 = 0, a2 = 0, a3 = 0;
    int b0 = 0, b1 = 0, b2 = 0, b3 = 0;
    const uint4* __restrict__ p = in4 + idx;

#pragma unroll
    for (int v = 0; v < V; v += 2) {
        uint4 x = __ldcs(&p[(long long)v * n4]);
        a0 += (x.x != 0u); a1 += (x.y != 0u);
        a2 += (x.z != 0u); a3 += (x.w != 0u);
        if (v + 1 < V) {
            uint4 y = __ldcs(&p[(long long)(v + 1) * n4]);
            b0 += (y.x != 0u); b1 += (y.y != 0u);
            b2 += (y.z != 0u); b3 += (y.w != 0u);
        }
    }

    const int s0 = a0 + b0, s1 = a1 + b1, s2 = a2 + b2, s3 = a3 + b3;
    float4 o;
    o.x = (2 * s0 > V) ? 1.0f : 0.0f;
    o.y = (2 * s1 > V) ? 1.0f : 0.0f;
    o.z = (2 * s2 > V) ? 1.0f : 0.0f;
    o.w = (2 * s3 > V) ? 1.0f : 0.0f;
    __stcs(&out4[idx], o);
}

// Runtime-V vectorized fallback.
__global__ __launch_bounds__(THREADS)
void vote_vec4_dyn(const uint4* __restrict__ in4,
                   float4* __restrict__ out4,
                   int n4, int V) {
    const int idx = blockIdx.x * THREADS + threadIdx.x;
    if (idx >= n4) return;
    int s0 = 0, s1 = 0, s2 = 0, s3 = 0;
#pragma unroll 8
    for (int v = 0; v < V; v++) {
        uint4 x = __ldcs(&in4[(long long)v * n4 + idx]);
        s0 += (x.x != 0u); s1 += (x.y != 0u);
        s2 += (x.z != 0u); s3 += (x.w != 0u);
    }
    float4 o;
    o.x = (2 * s0 > V) ? 1.0f : 0.0f;
    o.y = (2 * s1 > V) ? 1.0f : 0.0f;
    o.z = (2 * s2 > V) ? 1.0f : 0.0f;
    o.w = (2 * s3 > V) ? 1.0f : 0.0f;
    __stcs(&out4[idx], o);
}

// Scalar fallback for B % 4 != 0.
__global__ __launch_bounds__(THREADS)
void vote_scalar(const unsigned int* __restrict__ in,
                 float* __restrict__ out,
                 int B, int V) {
    int b = blockIdx.x * THREADS + threadIdx.x;
    const int stride = gridDim.x * THREADS;
    for (; b < B; b += stride) {
        int s = 0;
        for (int v = 0; v < V; v++) s += (in[(long long)v * B + b] != 0u);
        out[b] = (2 * s > V) ? 1.0f : 0.0f;
    }
}

extern "C" void kernel_launch(void* const* d_in, const int* in_sizes, int n_in,
                              void* d_out, int out_size) {
    const unsigned int* in = (const unsigned int*)d_in[0];
    float* out = (float*)d_out;

    const long long Sin = in_sizes[0];
    long long B = out_size;
    if (B <= 0) return;
    long long V = (Sin % B == 0) ? (Sin / B) : 31;
    if (V <= 0) V = 1;

    if (B % 4 == 0) {
        const int n4 = (int)(B / 4);
        const int blocks = (n4 + THREADS - 1) / THREADS;
        if (V == 31) {
            vote_vec4_oneshot<31><<<blocks, THREADS>>>(
                (const uint4*)in, (float4*)out, n4);
        } else {
            vote_vec4_dyn<<<blocks, THREADS>>>(
                (const uint4*)in, (float4*)out, n4, (int)V);
        }
    } else {
        int blocks = (int)((B + THREADS - 1) / THREADS);
        if (blocks > 148 * 32) blocks = 148 * 32;
        vote_scalar<<<blocks, THREADS>>>(in, out, (int)B, (int)V);
    }
}